// round 14
// baseline (speedup 1.0000x reference)
#include <cuda_runtime.h>
#include <math.h>

// CurveGraphic2d: 16 cubic Beziers -> 16 x 256x256 canvases.
// canvas = clip(1 - (min_d/w + eps)^aa, 0, 1); w <= 8 so min_d >= w gives
// exactly 0 -> block/warp culling is exact.
//
// Single kernel, 1024 blocks x 256 threads. Block = curve x 16x64 region.
// Warp = 4x32 tile (half-diag 15.57 -> tight cull); 4 px/thread -> one
// STG.128 per thread dead or alive. Block-level cull (computed inside the
// prelude shuffle tree) short-circuits ~60% of blocks to pure zero-stores.

#define CANVAS_H 256
#define CANVAS_W 256
#define NSAMP 32
#define MAX_LEN 300.0f
#define EPS 1e-6f

__global__ __launch_bounds__(256)
void curve_graphic_kernel(const float* __restrict__ inputs,   // [16,4,2]
                          const float* __restrict__ widths,   // [16]
                          const float* __restrict__ aafac,    // [16]
                          float* __restrict__ out)            // [16,256,256]
{
    __shared__ float4 ssamp[NSAMP / 2];   // 32 samples as (y,x) pairs
    __shared__ int s_blockdead;

    const int tid = threadIdx.x;
    const int b   = blockIdx.x >> 6;      // curve / canvas
    const int reg = blockIdx.x & 63;      // region: 16 rows x 64 cols
    const int ry0 = (reg >> 2) << 4;
    const int rx0 = (reg & 3) << 6;

    const float w = widths[b];

    // ---- Prelude: warp 0 computes the 32 sample points + block cull ----
    if (tid < 32) {
        const int s = tid;
        float cy[4], cx[4];
#pragma unroll
        for (int i = 0; i < 4; i++) {
            cy[i] = inputs[(b * 4 + i) * 2 + 0] * (float)CANVAS_H;
            cx[i] = inputs[(b * 4 + i) * 2 + 1] * (float)CANVAS_W;
        }

        const float t = (float)s / 31.0f;            // linspace(0,1,32)
        const float u = 1.0f - t;
        const float B0 = u * u * u;
        const float B1 = 3.0f * t * u * u;
        const float B2 = 3.0f * t * t * u;
        const float B3 = t * t * t;

        // Full-curve sample (arc length)
        const float py = B0 * cy[0] + B1 * cy[1] + B2 * cy[2] + B3 * cy[3];
        const float px = B0 * cx[0] + B1 * cx[1] + B2 * cx[2] + B3 * cx[3];

        const float pym = __shfl_up_sync(0xffffffffu, py, 1);
        const float pxm = __shfl_up_sync(0xffffffffu, px, 1);
        const float dyy = py - pym;
        const float dxx = px - pxm;
        float seg = (s > 0) ? sqrtf(dyy * dyy + dxx * dxx) : 0.0f;
#pragma unroll
        for (int off = 16; off; off >>= 1)
            seg += __shfl_xor_sync(0xffffffffu, seg, off);
        const float arc = seg;

        const float tt = fminf(1.0f, MAX_LEN / (arc + EPS));
        const float ut = 1.0f - tt;

        // de Casteljau left subdivision at tt
        const float b0y = ut * cy[0] + tt * cy[1], b0x = ut * cx[0] + tt * cx[1];
        const float b1y = ut * cy[1] + tt * cy[2], b1x = ut * cx[1] + tt * cx[2];
        const float b2y = ut * cy[2] + tt * cy[3], b2x = ut * cx[2] + tt * cx[3];
        const float c0y = ut * b0y + tt * b1y,     c0x = ut * b0x + tt * b1x;
        const float c1y = ut * b1y + tt * b2y,     c1x = ut * b1x + tt * b2x;
        const float d0y = ut * c0y + tt * c1y,     d0x = ut * c0x + tt * c1x;

        // Truncated-curve sample
        const float sy = B0 * cy[0] + B1 * b0y + B2 * c0y + B3 * d0y;
        const float sx = B0 * cx[0] + B1 * b0x + B2 * c0x + B3 * d0x;

        ((float2*)ssamp)[s] = make_float2(sy, sx);

        // Block cull: min squared distance from region center to samples.
        // Region pixel-center half-extents (7.5, 31.5) -> half-diag 32.3805.
        const float rdy = (float)ry0 + 7.5f  - sy;
        const float rdx = (float)rx0 + 31.5f - sx;
        float d2 = rdy * rdy + rdx * rdx;
#pragma unroll
        for (int off = 16; off; off >>= 1)
            d2 = fminf(d2, __shfl_xor_sync(0xffffffffu, d2, off));
        if (s == 0) {
            const float thr = w + 32.3805f + 1.0f;
            s_blockdead = (d2 >= thr * thr) ? 1 : 0;
        }
    }
    __syncthreads();

    // ---- Thread geometry: warp = 4x32 tile, 4 consecutive px per thread ----
    const int wid  = tid >> 5;
    const int lane = tid & 31;
    const int wry  = ry0 + ((wid >> 1) << 2);   // warp-tile row origin
    const int wrx  = rx0 + ((wid & 1) << 5);    // warp-tile col origin
    const int row  = wry + (lane >> 3);
    const int x0   = wrx + ((lane & 7) << 2);
    float4* const optr = (float4*)(out + (b << 16) + (row << 8) + x0);

    if (s_blockdead) {
        *optr = make_float4(0.f, 0.f, 0.f, 0.f);
        return;
    }

    // ---- Warp cull: min distance from 4x32 tile center to samples ----
    {
        const float2 sp = ((const float2*)ssamp)[lane];
        const float scy = (float)wry + 1.5f;
        const float scx = (float)wrx + 15.5f;
        const float ddy = scy - sp.x;
        const float ddx = scx - sp.y;
        float d2 = ddy * ddy + ddx * ddx;
#pragma unroll
        for (int off = 16; off; off >>= 1)
            d2 = fminf(d2, __shfl_xor_sync(0xffffffffu, d2, off));
        // Tile half-diagonal sqrt(1.5^2 + 15.5^2) = 15.572 + 1 px margin.
        const float thr = w + 15.572f + 1.0f;
        if (d2 >= thr * thr) {                    // warp-uniform
            *optr = make_float4(0.f, 0.f, 0.f, 0.f);
            return;
        }
    }

    // ---- Full evaluation: 4 pixels, min squared distance over 32 samples ----
    // (dxa+c)^2 + dy^2 = (dxa^2+dy^2) + 2c*dxa + c^2; track min(s + 2c*dxa)
    // per pixel (FFMA-imm + FMNMX), add c^2 once after the loop.
    const float fy = (float)row;
    const float fx = (float)x0;
    float m0 = 3.4e38f, m1 = 3.4e38f, m2 = 3.4e38f, m3 = 3.4e38f;
#pragma unroll
    for (int k = 0; k < NSAMP / 2; k++) {
        const float4 v = ssamp[k];                // LDS.128 broadcast, 2 samples
        {
            const float dy  = fy - v.x;
            const float dxa = fx - v.y;
            const float s2  = fmaf(dxa, dxa, dy * dy);
            m0 = fminf(m0, s2);
            m1 = fminf(m1, fmaf(2.0f, dxa, s2));
            m2 = fminf(m2, fmaf(4.0f, dxa, s2));
            m3 = fminf(m3, fmaf(6.0f, dxa, s2));
        }
        {
            const float dy  = fy - v.z;
            const float dxa = fx - v.w;
            const float s2  = fmaf(dxa, dxa, dy * dy);
            m0 = fminf(m0, s2);
            m1 = fminf(m1, fmaf(2.0f, dxa, s2));
            m2 = fminf(m2, fmaf(4.0f, dxa, s2));
            m3 = fminf(m3, fmaf(6.0f, dxa, s2));
        }
    }
    m1 += 1.0f; m2 += 4.0f; m3 += 9.0f;

    const float aa   = aafac[b];
    const float rinw = 1.0f / w;
    float4 r;
    r.x = fminf(fmaxf(1.0f - __powf(sqrtf(m0) * rinw + EPS, aa), 0.0f), 1.0f);
    r.y = fminf(fmaxf(1.0f - __powf(sqrtf(m1) * rinw + EPS, aa), 0.0f), 1.0f);
    r.z = fminf(fmaxf(1.0f - __powf(sqrtf(m2) * rinw + EPS, aa), 0.0f), 1.0f);
    r.w = fminf(fmaxf(1.0f - __powf(sqrtf(m3) * rinw + EPS, aa), 0.0f), 1.0f);
    *optr = r;
}

extern "C" void kernel_launch(void* const* d_in, const int* in_sizes, int n_in,
                              void* d_out, int out_size)
{
    const float* inputs = (const float*)d_in[0];   // [16,4,2]
    const float* widths = (const float*)d_in[1];   // [16]
    const float* aafac  = (const float*)d_in[2];   // [16]
    float* out = (float*)d_out;                    // [16,256,256]

    curve_graphic_kernel<<<1024, 256>>>(inputs, widths, aafac, out);
}

// round 17
// speedup vs baseline: 1.3462x; 1.3462x over previous
#include <cuda_runtime.h>
#include <math.h>

// CurveGraphic2d: 16 cubic Beziers -> 16 x 256x256 canvases.
// canvas = clip(1 - (min_d/w + eps)^aa, 0, 1); w <= 8 so min_d >= w gives
// exactly 0 -> block/warp culling is exact, and samples farther than
// w + tile_half_diag + margin from the tile center can be dropped from the
// per-pixel min without changing any emitted value.
//
// Single kernel, 1024 blocks x 256 threads. Block = curve x 16x64 region.
// Warp = 4x32 tile; 4 px/thread -> one STG.128 per thread dead or alive.
// Warp cull + relevant-sample set come from ONE ballot (no shuffle tree);
// eval iterates only the ballot's set bits (~5-10 samples instead of 32).

#define CANVAS_H 256
#define CANVAS_W 256
#define NSAMP 32
#define MAX_LEN 300.0f
#define EPS 1e-6f

__global__ __launch_bounds__(256)
void curve_graphic_kernel(const float* __restrict__ inputs,   // [16,4,2]
                          const float* __restrict__ widths,   // [16]
                          const float* __restrict__ aafac,    // [16]
                          float* __restrict__ out)            // [16,256,256]
{
    __shared__ float2 ssamp[NSAMP];       // 32 samples (y, x)
    __shared__ int s_blockdead;

    const int tid = threadIdx.x;
    const int b   = blockIdx.x >> 6;      // curve / canvas
    const int reg = blockIdx.x & 63;      // region: 16 rows x 64 cols
    const int ry0 = (reg >> 2) << 4;
    const int rx0 = (reg & 3) << 6;

    const float w = widths[b];

    // ---- Prelude: warp 0 computes the 32 sample points + block cull ----
    if (tid < 32) {
        const int s = tid;
        // Two LDG.128: control points for curve b (y0,x0,y1,x1 | y2,x2,y3,x3)
        const float4 cpa = ((const float4*)inputs)[b * 2 + 0];
        const float4 cpb = ((const float4*)inputs)[b * 2 + 1];
        const float cy0 = cpa.x * (float)CANVAS_H, cx0 = cpa.y * (float)CANVAS_W;
        const float cy1 = cpa.z * (float)CANVAS_H, cx1 = cpa.w * (float)CANVAS_W;
        const float cy2 = cpb.x * (float)CANVAS_H, cx2 = cpb.y * (float)CANVAS_W;
        const float cy3 = cpb.z * (float)CANVAS_H, cx3 = cpb.w * (float)CANVAS_W;

        const float t = (float)s / 31.0f;            // linspace(0,1,32)
        const float u = 1.0f - t;
        const float B0 = u * u * u;
        const float B1 = 3.0f * t * u * u;
        const float B2 = 3.0f * t * t * u;
        const float B3 = t * t * t;

        // Full-curve sample (arc length)
        const float py = B0 * cy0 + B1 * cy1 + B2 * cy2 + B3 * cy3;
        const float px = B0 * cx0 + B1 * cx1 + B2 * cx2 + B3 * cx3;

        const float pym = __shfl_up_sync(0xffffffffu, py, 1);
        const float pxm = __shfl_up_sync(0xffffffffu, px, 1);
        const float dyy = py - pym;
        const float dxx = px - pxm;
        float seg = (s > 0) ? sqrtf(dyy * dyy + dxx * dxx) : 0.0f;
#pragma unroll
        for (int off = 16; off; off >>= 1)
            seg += __shfl_xor_sync(0xffffffffu, seg, off);
        const float arc = seg;

        const float tt = fminf(1.0f, MAX_LEN / (arc + EPS));
        const float ut = 1.0f - tt;

        // de Casteljau left subdivision at tt
        const float b0y = ut * cy0 + tt * cy1, b0x = ut * cx0 + tt * cx1;
        const float b1y = ut * cy1 + tt * cy2, b1x = ut * cx1 + tt * cx2;
        const float b2y = ut * cy2 + tt * cy3, b2x = ut * cx2 + tt * cx3;
        const float c0y = ut * b0y + tt * b1y, c0x = ut * b0x + tt * b1x;
        const float c1y = ut * b1y + tt * b2y, c1x = ut * b1x + tt * b2x;
        const float d0y = ut * c0y + tt * c1y, d0x = ut * c0x + tt * c1x;

        // Truncated-curve sample
        const float sy = B0 * cy0 + B1 * b0y + B2 * c0y + B3 * d0y;
        const float sx = B0 * cx0 + B1 * b0x + B2 * c0x + B3 * d0x;

        ssamp[s] = make_float2(sy, sx);

        // Block cull: ballot instead of shuffle-min tree.
        // Region pixel-center half-extents (7.5, 31.5) -> half-diag 32.3805.
        const float rdy = (float)ry0 + 7.5f  - sy;
        const float rdx = (float)rx0 + 31.5f - sx;
        const float d2  = rdy * rdy + rdx * rdx;
        const float thr = w + 32.3805f + 1.0f;
        const unsigned bm = __ballot_sync(0xffffffffu, d2 < thr * thr);
        if (s == 0) s_blockdead = (bm == 0u) ? 1 : 0;
    }
    __syncthreads();

    // ---- Thread geometry: warp = 4x32 tile, 4 consecutive px per thread ----
    const int wid  = tid >> 5;
    const int lane = tid & 31;
    const int wry  = ry0 + ((wid >> 1) << 2);   // warp-tile row origin
    const int wrx  = rx0 + ((wid & 1) << 5);    // warp-tile col origin
    const int row  = wry + (lane >> 3);
    const int x0   = wrx + ((lane & 7) << 2);
    float4* const optr = (float4*)(out + (b << 16) + (row << 8) + x0);

    if (s_blockdead) {
        *optr = make_float4(0.f, 0.f, 0.f, 0.f);
        return;
    }

    // ---- Warp cull + relevant-sample mask via ONE ballot ----
    // Sample 'lane' is relevant iff dist(sample, tile_center) < w + 16.572
    // (tile half-diag sqrt(1.5^2+15.5^2)=15.572 + 1 px margin). Irrelevant
    // samples give d > w for every tile pixel -> dropping them is exact.
    unsigned mask;
    {
        const float2 sp = ssamp[lane];
        const float scy = (float)wry + 1.5f;
        const float scx = (float)wrx + 15.5f;
        const float ddy = scy - sp.x;
        const float ddx = scx - sp.y;
        const float d2  = ddy * ddy + ddx * ddx;
        const float thr = w + 16.572f;
        mask = __ballot_sync(0xffffffffu, d2 < thr * thr);
        if (mask == 0u) {                          // warp-uniform
            *optr = make_float4(0.f, 0.f, 0.f, 0.f);
            return;
        }
    }

    // ---- Sparse evaluation: only relevant samples, 4 pixels per thread ----
    // (dxa+c)^2 + dy^2 = s2 + 2c*dxa + c^2; track min(s2 + 2c*dxa) per pixel
    // (FFMA-imm + FMNMX), add c^2 once after the loop.
    const float fy = (float)row;
    const float fx = (float)x0;
    float m0 = 3.4e38f, m1 = 3.4e38f, m2 = 3.4e38f, m3 = 3.4e38f;
    while (mask) {
        const int i = __ffs(mask) - 1;
        mask &= mask - 1;
        const float2 v = ssamp[i];                 // LDS.64 broadcast
        const float dy  = fy - v.x;
        const float dxa = fx - v.y;
        const float s2  = fmaf(dxa, dxa, dy * dy);
        m0 = fminf(m0, s2);
        m1 = fminf(m1, fmaf(2.0f, dxa, s2));
        m2 = fminf(m2, fmaf(4.0f, dxa, s2));
        m3 = fminf(m3, fmaf(6.0f, dxa, s2));
    }
    m1 += 1.0f; m2 += 4.0f; m3 += 9.0f;

    const float aa   = aafac[b];
    const float rinw = 1.0f / w;
    float4 r;
    r.x = fminf(fmaxf(1.0f - __powf(sqrtf(m0) * rinw + EPS, aa), 0.0f), 1.0f);
    r.y = fminf(fmaxf(1.0f - __powf(sqrtf(m1) * rinw + EPS, aa), 0.0f), 1.0f);
    r.z = fminf(fmaxf(1.0f - __powf(sqrtf(m2) * rinw + EPS, aa), 0.0f), 1.0f);
    r.w = fminf(fmaxf(1.0f - __powf(sqrtf(m3) * rinw + EPS, aa), 0.0f), 1.0f);
    *optr = r;
}

extern "C" void kernel_launch(void* const* d_in, const int* in_sizes, int n_in,
                              void* d_out, int out_size)
{
    const float* inputs = (const float*)d_in[0];   // [16,4,2]
    const float* widths = (const float*)d_in[1];   // [16]
    const float* aafac  = (const float*)d_in[2];   // [16]
    float* out = (float*)d_out;                    // [16,256,256]

    curve_graphic_kernel<<<1024, 256>>>(inputs, widths, aafac, out);
}